// round 1
// baseline (speedup 1.0000x reference)
#include <cuda_runtime.h>
#include <math.h>

#define NB 64
#define TT 512
#define DD 1024
#define HH 1024

// Scratch for the precomputed input projection xh = x@W_xh + b_xh + b_hh.
// __device__ global (module-load allocation) — allowed; runtime allocs are not.
static __device__ float g_xh[(size_t)NB * TT * HH];

// ---------------------------------------------------------------------------
// Kernel A: xh = x @ W_xh + (b_xh + b_hh)
// Classic fp32 SGEMM: BM=BN=128, BK=8, 256 threads, 8x8 per-thread microtile.
// A: (32768 x 1024) row-major, B: (1024 x 1024) row-major, C row-major.
// ---------------------------------------------------------------------------
__global__ __launch_bounds__(256, 2)
void gemm_xh_kernel(const float* __restrict__ A, const float* __restrict__ B,
                    const float* __restrict__ bxh, const float* __restrict__ bhh)
{
    __shared__ float As[8][128];   // transposed: As[k][m]
    __shared__ float Bs[8][128];   // Bs[k][n]

    const int tid = threadIdx.x;
    const int bm = blockIdx.y * 128;
    const int bn = blockIdx.x * 128;
    const int tx = tid & 15;       // 0..15 -> col group
    const int ty = tid >> 4;       // 0..15 -> row group

    const int a_row = tid >> 1;          // 0..127
    const int a_col = (tid & 1) << 2;    // 0 or 4
    const int b_row = tid >> 5;          // 0..7
    const int b_col = (tid & 31) << 2;   // 0..124

    const float* Aptr = A + (size_t)(bm + a_row) * DD + a_col;
    const float* Bptr = B + (size_t)b_row * HH + bn + b_col;

    float acc[8][8];
#pragma unroll
    for (int i = 0; i < 8; ++i)
#pragma unroll
        for (int j = 0; j < 8; ++j) acc[i][j] = 0.0f;

    for (int k0 = 0; k0 < DD; k0 += 8) {
        float4 av = *(const float4*)(Aptr + k0);
        float4 bv = *(const float4*)(Bptr + (size_t)k0 * HH);
        As[a_col + 0][a_row] = av.x;
        As[a_col + 1][a_row] = av.y;
        As[a_col + 2][a_row] = av.z;
        As[a_col + 3][a_row] = av.w;
        *(float4*)&Bs[b_row][b_col] = bv;
        __syncthreads();

#pragma unroll
        for (int k = 0; k < 8; ++k) {
            float a_frag[8], b_frag[8];
            *(float4*)&a_frag[0] = *(const float4*)&As[k][ty * 8];
            *(float4*)&a_frag[4] = *(const float4*)&As[k][ty * 8 + 4];
            *(float4*)&b_frag[0] = *(const float4*)&Bs[k][tx * 8];
            *(float4*)&b_frag[4] = *(const float4*)&Bs[k][tx * 8 + 4];
#pragma unroll
            for (int i = 0; i < 8; ++i)
#pragma unroll
                for (int j = 0; j < 8; ++j)
                    acc[i][j] = fmaf(a_frag[i], b_frag[j], acc[i][j]);
        }
        __syncthreads();
    }

    // Epilogue: add both biases once, store float4s.
    float bsum[8];
#pragma unroll
    for (int j = 0; j < 8; ++j) {
        int col = bn + tx * 8 + j;
        bsum[j] = bxh[col] + bhh[col];
    }
#pragma unroll
    for (int i = 0; i < 8; ++i) {
        float* Crow = g_xh + (size_t)(bm + ty * 8 + i) * HH + bn + tx * 8;
        float4 o0, o1;
        o0.x = acc[i][0] + bsum[0];
        o0.y = acc[i][1] + bsum[1];
        o0.z = acc[i][2] + bsum[2];
        o0.w = acc[i][3] + bsum[3];
        o1.x = acc[i][4] + bsum[4];
        o1.y = acc[i][5] + bsum[5];
        o1.z = acc[i][6] + bsum[6];
        o1.w = acc[i][7] + bsum[7];
        *(float4*)(Crow + 0) = o0;
        *(float4*)(Crow + 4) = o1;
    }
}

// ---------------------------------------------------------------------------
// Kernel B: one recurrence step.
//   y[:, t, :] = tanh(xh[:, t, :] + y[:, t-1, :] @ W_hh)        (t > 0)
//   y[:, 0, :] = tanh(xh[:, 0, :])                              (t == 0)
//
// Grid 128 CTAs x 256 threads. CTA b owns 8 output columns [8b, 8b+8).
//   c  = tid & 7   : which of the 8 columns
//   kg = tid >> 3  : one of 32 k-groups; thread's k set is {kg + 32*i}, i<32
// W_hh slice lives in registers (32 floats/thread). h_{t-1} is staged to SMEM
// in 8-row chunks; the k-strided assignment makes warp LDS reads 4 adjacent
// words broadcast across 8 columns (conflict-free). Partials are reduced with
// shfl_xor over the kg lanes, then across warps via a small SMEM array.
// ---------------------------------------------------------------------------
__global__ __launch_bounds__(256, 1)
void rnn_step_kernel(float* __restrict__ y, const float* __restrict__ Whh, int t)
{
    const int tid = threadIdx.x;
    const int c_local = tid & 7;
    const int kg = tid >> 3;              // 0..31
    const int c0 = blockIdx.x * 8;
    const int c = c0 + c_local;
    const size_t nstride = (size_t)TT * HH;

    if (t == 0) {
        // h_prev = 0: pure elementwise tanh of xh.
        for (int idx = tid; idx < NB * 8; idx += 256) {
            int n = idx >> 3;
            int cc = c0 + (idx & 7);
            size_t off = (size_t)n * nstride + cc;   // t = 0
            y[off] = tanhf(g_xh[off]);
        }
        return;
    }

    __shared__ float hs[8][HH];        // 8 rows of h_{t-1}, 32 KB
    __shared__ float accs[8][8][8];    // [row][warp][col], 2 KB

    // Register-resident W_hh slice: w[i] = W_hh[kg + 32*i][c]
    float w[32];
#pragma unroll
    for (int i = 0; i < 32; ++i)
        w[i] = Whh[(size_t)(kg + (i << 5)) * HH + c];

    const int wid = tid >> 5;
    const int lane = tid & 31;

    for (int r0 = 0; r0 < NB; r0 += 8) {
        // Stage 8 rows of h_{t-1} (each warp copies one row, float4-coalesced).
        {
            const float4* s4 = (const float4*)(y + (size_t)(r0 + wid) * nstride
                                                 + (size_t)(t - 1) * HH);
            float4* dst = (float4*)&hs[wid][0];
#pragma unroll
            for (int j = 0; j < 8; ++j)
                dst[lane + j * 32] = s4[lane + j * 32];
        }
        __syncthreads();

#pragma unroll
        for (int r = 0; r < 8; ++r) {
            const float* hrow = &hs[r][kg];
            float p0 = 0.f, p1 = 0.f, p2 = 0.f, p3 = 0.f;
#pragma unroll
            for (int i = 0; i < 32; i += 4) {
                p0 = fmaf(hrow[(i + 0) << 5], w[i + 0], p0);
                p1 = fmaf(hrow[(i + 1) << 5], w[i + 1], p1);
                p2 = fmaf(hrow[(i + 2) << 5], w[i + 2], p2);
                p3 = fmaf(hrow[(i + 3) << 5], w[i + 3], p3);
            }
            float p = (p0 + p1) + (p2 + p3);
            // Reduce over the 4 kg groups inside the warp (lane bits 3,4).
            p += __shfl_xor_sync(0xffffffffu, p, 8);
            p += __shfl_xor_sync(0xffffffffu, p, 16);
            if (lane < 8)
                accs[r][wid][lane] = p;   // lane == c_local here
        }
        __syncthreads();

        // Cross-warp reduce + tanh + store (64 outputs per chunk).
        if (tid < 64) {
            int r = tid >> 3;
            int cc = tid & 7;
            float s = 0.f;
#pragma unroll
            for (int wv = 0; wv < 8; ++wv) s += accs[r][wv][cc];
            size_t off = (size_t)(r0 + r) * nstride + (size_t)t * HH + (c0 + cc);
            y[off] = tanhf(g_xh[off] + s);
        }
        __syncthreads();
    }
}

// ---------------------------------------------------------------------------
// Launch: inputs in metadata order: x, weight_xh, weight_hh, bias_xh, bias_hh.
// Graph-capturable: plain kernel launches on the capture stream only.
// ---------------------------------------------------------------------------
extern "C" void kernel_launch(void* const* d_in, const int* in_sizes, int n_in,
                              void* d_out, int out_size)
{
    const float* x   = (const float*)d_in[0];
    const float* wxh = (const float*)d_in[1];
    const float* whh = (const float*)d_in[2];
    const float* bxh = (const float*)d_in[3];
    const float* bhh = (const float*)d_in[4];
    float* y = (float*)d_out;

    (void)in_sizes; (void)n_in; (void)out_size;

    dim3 g1(HH / 128, (NB * TT) / 128);   // (8, 256)
    gemm_xh_kernel<<<g1, 256>>>(x, wxh, bxh, bhh);

    for (int t = 0; t < TT; ++t)
        rnn_step_kernel<<<128, 256>>>(y, whh, t);
}

// round 4
// speedup vs baseline: 1.2766x; 1.2766x over previous
#include <cuda_runtime.h>
#include <math.h>

#define NB 64
#define TT 512
#define DD 1024
#define HH 1024

// Scratch for xh = x@W_xh + b_xh + b_hh (128 MB, module-load alloc: allowed)
static __device__ float g_xh[(size_t)NB * TT * HH];

// ---------------------------------------------------------------------------
// Kernel A: xh = x @ W_xh + (b_xh + b_hh)
// fp32 SGEMM: BM=BN=128, BK=8, 256 threads, 8x8 microtile.
// ---------------------------------------------------------------------------
__global__ __launch_bounds__(256, 2)
void gemm_xh_kernel(const float* __restrict__ A, const float* __restrict__ B,
                    const float* __restrict__ bxh, const float* __restrict__ bhh)
{
    __shared__ float As[8][128];
    __shared__ float Bs[8][128];

    const int tid = threadIdx.x;
    const int bm = blockIdx.y * 128;
    const int bn = blockIdx.x * 128;
    const int tx = tid & 15;
    const int ty = tid >> 4;

    const int a_row = tid >> 1;
    const int a_col = (tid & 1) << 2;
    const int b_row = tid >> 5;
    const int b_col = (tid & 31) << 2;

    const float* Aptr = A + (size_t)(bm + a_row) * DD + a_col;
    const float* Bptr = B + (size_t)b_row * HH + bn + b_col;

    float acc[8][8];
#pragma unroll
    for (int i = 0; i < 8; ++i)
#pragma unroll
        for (int j = 0; j < 8; ++j) acc[i][j] = 0.0f;

    for (int k0 = 0; k0 < DD; k0 += 8) {
        float4 av = *(const float4*)(Aptr + k0);
        float4 bv = *(const float4*)(Bptr + (size_t)k0 * HH);
        As[a_col + 0][a_row] = av.x;
        As[a_col + 1][a_row] = av.y;
        As[a_col + 2][a_row] = av.z;
        As[a_col + 3][a_row] = av.w;
        *(float4*)&Bs[b_row][b_col] = bv;
        __syncthreads();

#pragma unroll
        for (int k = 0; k < 8; ++k) {
            float a_frag[8], b_frag[8];
            *(float4*)&a_frag[0] = *(const float4*)&As[k][ty * 8];
            *(float4*)&a_frag[4] = *(const float4*)&As[k][ty * 8 + 4];
            *(float4*)&b_frag[0] = *(const float4*)&Bs[k][tx * 8];
            *(float4*)&b_frag[4] = *(const float4*)&Bs[k][tx * 8 + 4];
#pragma unroll
            for (int i = 0; i < 8; ++i)
#pragma unroll
                for (int j = 0; j < 8; ++j)
                    acc[i][j] = fmaf(a_frag[i], b_frag[j], acc[i][j]);
        }
        __syncthreads();
    }

    float bsum[8];
#pragma unroll
    for (int j = 0; j < 8; ++j) {
        int col = bn + tx * 8 + j;
        bsum[j] = bxh[col] + bhh[col];
    }
#pragma unroll
    for (int i = 0; i < 8; ++i) {
        float* Crow = g_xh + (size_t)(bm + ty * 8 + i) * HH + bn + tx * 8;
        float4 o0, o1;
        o0.x = acc[i][0] + bsum[0]; o0.y = acc[i][1] + bsum[1];
        o0.z = acc[i][2] + bsum[2]; o0.w = acc[i][3] + bsum[3];
        o1.x = acc[i][4] + bsum[4]; o1.y = acc[i][5] + bsum[5];
        o1.z = acc[i][6] + bsum[6]; o1.w = acc[i][7] + bsum[7];
        *(float4*)(Crow + 0) = o0;
        *(float4*)(Crow + 4) = o1;
    }
}

// ---------------------------------------------------------------------------
// Kernel B: one recurrence step (one launch per t — proven stable structure).
//   y[:, t, :] = tanh(xh[:, t, :] + y[:, t-1, :] @ W_hh)    (t > 0)
//   y[:, 0, :] = tanh(xh[:, 0, :])                          (t == 0)
//
// 128 CTAs x 512 threads. CTA owns 8 output cols [8b, 8b+8).
//   c_local = tid & 7, kq = tid >> 3 (0..63): thread covers k in
//   [16*kq, 16*kq+16) for its single column. w[16] register-resident.
// h_{t-1} staged in 8-row chunks into PADDED smem (4-float pad per 16-float
// block, row stride 1280 floats): the 4 kq-groups of a warp read from
// disjoint bank quadrants -> every LDS.128 is a single crossbar phase.
// Reduce: shfl over the 4 in-warp kq groups, cross-warp via padded accs.
// ---------------------------------------------------------------------------
#define RS4 320   // hs row stride in float4 units (1280 floats)

__global__ __launch_bounds__(512, 1)
void rnn_step_kernel(float* __restrict__ y, const float* __restrict__ Whh, int t)
{
    __shared__ float4 hs[8 * RS4];     // 40960 B, padded
    __shared__ float  accs[8 * 136];   //  4352 B, row stride 136 (pad 8)
    __shared__ float  xh_s[512];       //  2048 B

    const int tid = threadIdx.x;
    const int lane = tid & 31;
    const int wid = tid >> 5;           // 0..15
    const int c_local = tid & 7;
    const int kq = tid >> 3;            // 0..63
    const int c0 = blockIdx.x * 8;
    const size_t nstride = (size_t)TT * HH;

    // This thread's owned output (row = tid>>3, col = c0 + c_local)
    const int orow = tid >> 3;
    const size_t ooff = (size_t)orow * nstride + (size_t)t * HH + (c0 + c_local);

    if (t == 0) {
        y[ooff] = tanhf(g_xh[ooff]);
        return;
    }

    // W_hh slice into registers: w[i] = Whh[16*kq + i][c0 + c_local]
    float w[16];
    {
        const float* wp = Whh + (size_t)(kq << 4) * HH + (c0 + c_local);
#pragma unroll
        for (int i = 0; i < 16; ++i)
            w[i] = wp[(size_t)i * HH];
    }

    // Prefetch this thread's xh value (hides DRAM latency behind staging)
    float xh_val = g_xh[ooff];

    const float* hprev = y + (size_t)(t - 1) * HH;   // + n*nstride per row
    const int srow = tid >> 6;          // 0..7  (staging row within chunk)
    const int sblk = tid & 63;          // 0..63 (16-float block within row)

    // Stage chunk 0 (rows 0..7 of h_{t-1})
    {
        const float4* src = (const float4*)(hprev + (size_t)srow * nstride) + sblk * 4;
        float4 v0 = src[0], v1 = src[1], v2 = src[2], v3 = src[3];
        float4* dst = hs + srow * RS4 + sblk * 5;   // 5 f4 per 16-float block (1 pad)
        dst[0] = v0; dst[1] = v1; dst[2] = v2; dst[3] = v3;
    }
    xh_s[tid] = xh_val;
    __syncthreads();

    for (int ch = 0; ch < 8; ++ch) {
        // ---- compute 8 rows of this chunk ----
#pragma unroll
        for (int r = 0; r < 8; ++r) {
            const float4* hp = hs + r * RS4 + kq * 5;
            float4 h0 = hp[0], h1 = hp[1], h2 = hp[2], h3 = hp[3];
            float p0, p1, p2, p3;
            p0 = h0.x * w[0];           p1 = h0.y * w[1];
            p2 = h0.z * w[2];           p3 = h0.w * w[3];
            p0 = fmaf(h1.x, w[4],  p0); p1 = fmaf(h1.y, w[5],  p1);
            p2 = fmaf(h1.z, w[6],  p2); p3 = fmaf(h1.w, w[7],  p3);
            p0 = fmaf(h2.x, w[8],  p0); p1 = fmaf(h2.y, w[9],  p1);
            p2 = fmaf(h2.z, w[10], p2); p3 = fmaf(h2.w, w[11], p3);
            p0 = fmaf(h3.x, w[12], p0); p1 = fmaf(h3.y, w[13], p1);
            p2 = fmaf(h3.z, w[14], p2); p3 = fmaf(h3.w, w[15], p3);
            float p = (p0 + p1) + (p2 + p3);
            // reduce over the 4 kq groups inside the warp (lane bits 3,4)
            p += __shfl_xor_sync(0xffffffffu, p, 8);
            p += __shfl_xor_sync(0xffffffffu, p, 16);
            if (lane < 8)
                accs[r * 136 + wid * 8 + lane] = p;
        }
        __syncthreads();

        // ---- stage next chunk (all threads) — hs reads of ch are done ----
        if (ch < 7) {
            const float4* src = (const float4*)(hprev
                + (size_t)(((ch + 1) << 3) + srow) * nstride) + sblk * 4;
            float4 v0 = src[0], v1 = src[1], v2 = src[2], v3 = src[3];
            float4* dst = hs + srow * RS4 + sblk * 5;
            dst[0] = v0; dst[1] = v1; dst[2] = v2; dst[3] = v3;
        }

        // ---- cross-warp reduce + tanh + store (64 outputs, tid<64) ----
        if (tid < 64) {
            int rl = tid >> 3;
            int cc = tid & 7;
            const float* ap = accs + rl * 136 + cc;
            float s = 0.0f;
#pragma unroll
            for (int wv = 0; wv < 16; ++wv) s += ap[wv * 8];
            int row = (ch << 3) + rl;
            size_t off = (size_t)row * nstride + (size_t)t * HH + (c0 + cc);
            y[off] = tanhf(xh_s[(row << 3) + cc] + s);
        }
        __syncthreads();   // accs reusable, hs(ch+1) visible
    }
}

// ---------------------------------------------------------------------------
// Launch. Inputs: x, weight_xh, weight_hh, bias_xh, bias_hh.
// Pure kernel launches — graph-capturable, no attributes, no device state.
// ---------------------------------------------------------------------------
extern "C" void kernel_launch(void* const* d_in, const int* in_sizes, int n_in,
                              void* d_out, int out_size)
{
    const float* x   = (const float*)d_in[0];
    const float* wxh = (const float*)d_in[1];
    const float* whh = (const float*)d_in[2];
    const float* bxh = (const float*)d_in[3];
    const float* bhh = (const float*)d_in[4];
    float* y = (float*)d_out;

    (void)in_sizes; (void)n_in; (void)out_size;

    dim3 g1(HH / 128, (NB * TT) / 128);   // (8, 256)
    gemm_xh_kernel<<<g1, 256>>>(x, wxh, bxh, bhh);

    for (int t = 0; t < TT; ++t)
        rnn_step_kernel<<<128, 512>>>(y, whh, t);
}